// round 17
// baseline (speedup 1.0000x reference)
#include <cuda_runtime.h>
#include <math.h>
#include <float.h>
#include <stdint.h>

// MoE gate: logits = hidden @ gate^T ; softmax over 8 experts; top-2; renormalize.
// hidden: [T, 4096] f32 (T = 16384), gate: [8, 4096] f32.
// Output (flattened f32): [T*2] topk weights, then [T*2] expert indices (as float).
//
// R15 L1-wavefront design (16 tokens/warp, gate through smem with
// broadcast-deduped LDS, per-warp cp.async rings, no block barriers) with the
// pipeline de-sawtoothed: NSTAGE=4 and the refill ISSUE hoisted ABOVE
// wait_group, so every warp holds exactly 3 chunks (9KB) in flight at all
// times including during the FMA burst (R15 dropped to 1 pending chunk during
// compute -> DRAM duty-cycled at 68% / 5.4 TB/s).
// (Resubmission: previous round died to container infra, same signature as the
// R13 flake whose identical kernel later passed.)

#define NEXP   8
#define HDIM   4096
#define HV     (HDIM / 4)      // 1024 float4 per row
#define HSPLIT 2
#define HHV    (HV / HSPLIT)   // 512 float4 per half
#define ITERS  (HHV / 8)       // 64 iters (8 float4 of h per half per iter)
#define NTILES (HV / 8)        // 128 one-KB gate tiles
#define TOK_PER_BLOCK 16
#define NSTAGE 4               // ring depth (x: 2KB/stage, gate: 1KB/stage)

// Packed gate: tile t (8 float4 of h), chunk c = i*8+j = float4 of expert values
//   s = i>>1, epb = (i&1)*2, h = (t*8+j)*4 + s
//   chunk = ( g[2epb][h], g[2epb+1][h], g[2epb+2][h], g[2epb+3][h] )
__device__ float4 g_packed[NTILES * 64];   // 128 KB

__global__ void pack_gate_kernel(const float* __restrict__ gate)
{
    const int tid = blockIdx.x * blockDim.x + threadIdx.x;
    if (tid >= NTILES * 64) return;
    const int t = tid >> 6, r = tid & 63, i = r >> 3, j = r & 7;
    const int s = i >> 1, epb = (i & 1) * 2;
    const int h = (t * 8 + j) * 4 + s;
    float4 v;
    v.x = gate[(2 * epb + 0) * HDIM + h];
    v.y = gate[(2 * epb + 1) * HDIM + h];
    v.z = gate[(2 * epb + 2) * HDIM + h];
    v.w = gate[(2 * epb + 3) * HDIM + h];
    g_packed[t * 64 + i * 8 + j] = v;
}

#define FMA2(acc, a, b) \
    asm("fma.rn.f32x2 %0, %1, %2, %0;" : "+l"(acc) : "l"(a), "l"(b))
#define ADD2(d, a, b) \
    asm("add.rn.f32x2 %0, %1, %2;" : "=l"(d) : "l"(a), "l"(b))
#define PACK_DUP2(o, f) \
    asm("mov.b64 %0, {%1, %1};" : "=l"(o) : "r"(__float_as_uint(f)))
#define UNPACK2(lo, hi, v) \
    asm("mov.b64 {%0, %1}, %2;" : "=r"(lo), "=r"(hi) : "l"(v))
#define CP16(dst, src) \
    asm volatile("cp.async.cg.shared.global [%0], [%1], 16;" :: "r"(dst), "l"(src))

// Issue chunk 'itc' (x: 2KB = 16 tokens x 128B of h; gate: 1KB = tile itc)
// into ring stage 'slot'. Lane (grp,j): x -> its 4 tokens at its j (issuer ==
// reader); gate -> chunks lane, lane+32 (contiguous 512B per cp, no dup).
// Commit is UNCONDITIONAL so per-thread group numbering stays: group g == chunk g.
#define ISSUE(slot, itc)                                                     \
    do {                                                                     \
        if ((itc) < ITERS) {                                                 \
            const float4* xs_ = xs + (size_t)(itc) * 8;                      \
            const uint32_t bx = dx + (uint32_t)(slot) * 2048u;               \
            CP16(bx + 0u * 128u, xs_ + 0 * HV);                              \
            CP16(bx + 1u * 128u, xs_ + 1 * HV);                              \
            CP16(bx + 2u * 128u, xs_ + 2 * HV);                              \
            CP16(bx + 3u * 128u, xs_ + 3 * HV);                              \
            const float4* gs_ = gs + (size_t)(itc) * 64;                     \
            const uint32_t bg = dg + (uint32_t)(slot) * 1024u;               \
            CP16(bg, gs_);                                                   \
            CP16(bg + 512u, gs_ + 32);                                       \
        }                                                                    \
        asm volatile("cp.async.commit_group;");                              \
    } while (0)

__global__ __launch_bounds__(64) void moe_gate_kernel(
    const float4* __restrict__ hid,
    float* __restrict__ out,
    int n_tokens)
{
    __shared__ float4 ring_x[2][NSTAGE][TOK_PER_BLOCK][8];  // 16 KB
    __shared__ float4 ring_g[2][NSTAGE][64];                //  8 KB
    __shared__ float  part[2][TOK_PER_BLOCK][NEXP];         //  1 KB

    const int lane = threadIdx.x & 31;
    const int half = threadIdx.x >> 5;   // 0..1: h-half (both warps: same 16 tokens)
    const int grp  = lane >> 3;          // 0..3: owns tokens grp*4 .. grp*4+3
    const int j    = lane & 7;           // h-sub position

    const int tok_base = blockIdx.x * TOK_PER_BLOCK;
    if (tok_base >= n_tokens) return;

    // lane-fixed source bases
    const float4* xs = hid + (size_t)(tok_base + grp * 4) * HV + half * HHV + j;
    const float4* gs = g_packed + (size_t)(half * ITERS) * 64 + lane;

    // lane-fixed ring destinations (stage 0)
    const uint32_t dx = (uint32_t)__cvta_generic_to_shared(
                            &ring_x[half][0][grp * 4][j]);
    const uint32_t dg = (uint32_t)__cvta_generic_to_shared(
                            &ring_g[half][0][lane]);

    uint64_t acc[4][4];   // [token-in-grp][expert-pair]
    #pragma unroll
    for (int t = 0; t < 4; t++)
        #pragma unroll
        for (int ep = 0; ep < 4; ep++)
            acc[t][ep] = 0ull;

    // prologue: stages 0..2 <- chunks 0..2 (groups 0..2)
    #pragma unroll
    for (int s = 0; s < NSTAGE - 1; s++)
        ISSUE(s, s);

    #pragma unroll 1
    for (int it = 0; it < ITERS; it++) {
        // refill FIRST: keeps 3 chunks pending through the whole compute burst.
        // Write slot (it+3)&3 == (it-1)&3: that slot's LDS reads (x and gate,
        // all lanes, warp-lockstep) completed at iteration it-1, before this
        // point in program order.
        ISSUE((it + 3) & 3, it + 3);

        // groups committed = it+4; wait <=3 pending -> chunk 'it' complete
        asm volatile("cp.async.wait_group 3;");
        __syncwarp();   // gate chunks were written by sibling lanes

        const int sl = it & 3;

        // x: this lane's own 4 tokens at its j
        const float4 xv0 = ring_x[half][sl][grp * 4 + 0][j];
        const float4 xv1 = ring_x[half][sl][grp * 4 + 1][j];
        const float4 xv2 = ring_x[half][sl][grp * 4 + 2][j];
        const float4 xv3 = ring_x[half][sl][grp * 4 + 3][j];
        const float* xf0 = &xv0.x;
        const float* xf1 = &xv1.x;
        const float* xf2 = &xv2.x;
        const float* xf3 = &xv3.x;

        #pragma unroll
        for (int sc = 0; sc < 4; sc++) {
            // gate chunks (i=2sc, 2sc+1) at this j — smem broadcast across grps
            const ulonglong2 gA = *(const ulonglong2*)&ring_g[half][sl][16 * sc + j];
            const ulonglong2 gB = *(const ulonglong2*)&ring_g[half][sl][16 * sc + 8 + j];
            uint64_t p0, p1, p2, p3;
            PACK_DUP2(p0, xf0[sc]);
            PACK_DUP2(p1, xf1[sc]);
            PACK_DUP2(p2, xf2[sc]);
            PACK_DUP2(p3, xf3[sc]);
            FMA2(acc[0][0], p0, gA.x); FMA2(acc[0][1], p0, gA.y);
            FMA2(acc[0][2], p0, gB.x); FMA2(acc[0][3], p0, gB.y);
            FMA2(acc[1][0], p1, gA.x); FMA2(acc[1][1], p1, gA.y);
            FMA2(acc[1][2], p1, gB.x); FMA2(acc[1][3], p1, gB.y);
            FMA2(acc[2][0], p2, gA.x); FMA2(acc[2][1], p2, gA.y);
            FMA2(acc[2][2], p2, gB.x); FMA2(acc[2][3], p2, gB.y);
            FMA2(acc[3][0], p3, gA.x); FMA2(acc[3][1], p3, gA.y);
            FMA2(acc[3][2], p3, gB.x); FMA2(acc[3][3], p3, gB.y);
        }
    }

    // reduce over the 8 j-lanes of each grp (masks 1,2,4 stay within the grp)
    #pragma unroll
    for (int t = 0; t < 4; t++)
        #pragma unroll
        for (int ep = 0; ep < 4; ep++) {
            uint64_t v = acc[t][ep], o;
            o = __shfl_xor_sync(0xffffffffu, (unsigned long long)v, 1); ADD2(v, v, o);
            o = __shfl_xor_sync(0xffffffffu, (unsigned long long)v, 2); ADD2(v, v, o);
            o = __shfl_xor_sync(0xffffffffu, (unsigned long long)v, 4); ADD2(v, v, o);
            acc[t][ep] = v;
        }

    if (j == 0) {
        #pragma unroll
        for (int t = 0; t < 4; t++)
            #pragma unroll
            for (int ep = 0; ep < 4; ep++) {
                unsigned lo, hi;
                UNPACK2(lo, hi, acc[t][ep]);
                part[half][grp * 4 + t][2 * ep + 0] = __uint_as_float(lo);
                part[half][grp * 4 + t][2 * ep + 1] = __uint_as_float(hi);
            }
    }
    __syncthreads();

    // finalize: threads 0..15 -> one token each
    if (threadIdx.x < TOK_PER_BLOCK) {
        const int tid   = threadIdx.x;
        const int token = tok_base + tid;
        if (token < n_tokens) {
            float l[NEXP];
            #pragma unroll
            for (int q = 0; q < NEXP; q++)
                l[q] = part[0][tid][q] + part[1][tid][q];

            // top-1 (strict > keeps lowest index on ties, matching lax.top_k)
            float b0 = l[0]; int i0 = 0;
            #pragma unroll
            for (int q = 1; q < NEXP; q++)
                if (l[q] > b0) { b0 = l[q]; i0 = q; }

            // top-2
            float b1 = -FLT_MAX; int i1 = 0;
            #pragma unroll
            for (int q = 0; q < NEXP; q++)
                if (q != i0 && l[q] > b1) { b1 = l[q]; i1 = q; }

            // renormalized top-2 softmax: w0 = e^{l0} / (e^{l0} + e^{l1})
            const float w0 = 1.0f / (1.0f + expf(b1 - b0));
            const float w1 = 1.0f - w0;

            float* out_idx = out + (size_t)n_tokens * 2;
            out[token * 2 + 0] = w0;
            out[token * 2 + 1] = w1;
            out_idx[token * 2 + 0] = (float)i0;
            out_idx[token * 2 + 1] = (float)i1;
        }
    }
}

extern "C" void kernel_launch(void* const* d_in, const int* in_sizes, int n_in,
                              void* d_out, int out_size)
{
    const float* hid  = (const float*)d_in[0];   // hidden_states
    const float* gate = (const float*)d_in[1];   // gate_weight
    float* out = (float*)d_out;

    const int n_tokens = in_sizes[0] / HDIM;     // 16384

    pack_gate_kernel<<<(NTILES * 64 + 255) / 256, 256>>>(gate);

    const int blocks = (n_tokens + TOK_PER_BLOCK - 1) / TOK_PER_BLOCK;  // 1024
    moe_gate_kernel<<<blocks, 64>>>((const float4*)hid, out, n_tokens);
}